// round 9
// baseline (speedup 1.0000x reference)
#include <cuda_runtime.h>
#include <cuda_fp16.h>
#include <cstdint>

// Problem shapes
#define NB    16
#define C_IN  64
#define H_IN  128
#define W_IN  128
#define K_OUT 128
#define P_OUT 126
#define Q_OUT 126
#define PQ    (P_OUT * Q_OUT)

// ---------------- scratch (device globals: allocation-free) ----------------
// +1024 halves of pad: row-ring loads read up to 2 q-rows past the last image row.
__device__ __align__(1024) __half g_input_h[(size_t)NB * H_IN * W_IN * C_IN + 1024]; // NHWC fp16
__device__ __align__(1024) __half g_w9[9 * K_OUT * C_IN];                             // [rs][k][c]

// ---------------- PTX helpers (all sm_80-level: works on compute_103) ----------------
__device__ __forceinline__ uint32_t smem_u32(const void* p) {
    uint32_t a;
    asm("{ .reg .u64 t; cvta.to.shared.u64 t, %1; cvt.u32.u64 %0, t; }" : "=r"(a) : "l"(p));
    return a;
}

#define CP_ASYNC16(dst, src) \
    asm volatile("cp.async.cg.shared.global [%0], [%1], 16;\n" :: "r"(dst), "l"(src) : "memory")
#define CP_COMMIT() asm volatile("cp.async.commit_group;\n" ::: "memory")
#define CP_WAIT0()  asm volatile("cp.async.wait_group 0;\n" ::: "memory")

#define LDSM_X4(R, addr) \
    asm volatile("ldmatrix.sync.aligned.m8n8.x4.shared.b16 {%0,%1,%2,%3}, [%4];\n" \
        : "=r"((R)[0]), "=r"((R)[1]), "=r"((R)[2]), "=r"((R)[3]) : "r"(addr))

#define MMA16816(C, A, B0, B1) \
    asm volatile("mma.sync.aligned.m16n8k16.row.col.f32.f16.f16.f32 " \
        "{%0,%1,%2,%3}, {%4,%5,%6,%7}, {%8,%9}, {%0,%1,%2,%3};\n" \
        : "+f"((C)[0]), "+f"((C)[1]), "+f"((C)[2]), "+f"((C)[3]) \
        : "r"((A)[0]), "r"((A)[1]), "r"((A)[2]), "r"((A)[3]), "r"(B0), "r"(B1))

// ---------------- prologue kernels ----------------
// NCHW f32 -> NHWC fp16 (tiled transpose through smem)
__global__ void convert_input_kernel(const float* __restrict__ data) {
    __shared__ float s[64 * 33];
    const int w0 = blockIdx.x * 32, h = blockIdx.y, n = blockIdx.z;
    const int tid = threadIdx.x;
#pragma unroll
    for (int it = 0; it < 8; it++) {
        int i = it * 256 + tid;
        int c = i >> 5, w = i & 31;
        s[c * 33 + w] = data[(((size_t)n * C_IN + c) * H_IN + h) * W_IN + w0 + w];
    }
    __syncthreads();
    __half2* gp = (__half2*)g_input_h;
#pragma unroll
    for (int it = 0; it < 4; it++) {
        int i = it * 256 + tid;
        int w = i >> 5, cp = i & 31;
        float lo = s[(2 * cp) * 33 + w];
        float hi = s[(2 * cp + 1) * 33 + w];
        gp[(((size_t)n * H_IN + h) * W_IN + w0 + w) * 32 + cp] = __floats2half2_rn(lo, hi);
    }
}

// W[k,c,r,s] f32 -> g_w9[rs][k][c] fp16
__global__ void convert_weights_kernel(const float* __restrict__ w) {
    int i = blockIdx.x * 256 + threadIdx.x;
    if (i >= 9 * K_OUT * C_IN) return;
    int rs = i / (K_OUT * C_IN);
    int rem = i - rs * (K_OUT * C_IN);
    int k = rem >> 6, c = rem & 63;
    int r = rs / 3, s = rs - r * 3;
    g_w9[i] = __float2half(w[((k * C_IN + c) * 3 + r) * 3 + s]);
}

// ---------------- main mma.sync conv kernel ----------------
// 8 warps (2/SMSP), warp = (k-half, q-half, p-parity), each 64(k) x 64(q).
// CTA owns 14 CONTIGUOUS output rows of one image -> sliding 5-slot input
// row ring, each input row loaded exactly once (16 loads / 14 output rows).
#define NTHREADS 256
#define NCTA 144                      // 16 images x 9 chunks of 14 rows
#define NPAIRS 7                      // 7 row-pairs per CTA
#define W_SLOT 16384                  // 128 rows(k) x 128B(64 halves)
#define IN_ROWS 130                   // q-rows per input image row (incl. 2 pad reads)
#define IN_SLOT (IN_ROWS * 128)       // 16640 B
#define NRING 5
#define SM_IN_OFF (9 * W_SLOT)        // 147456
#define SM_TOTAL (SM_IN_OFF + NRING * IN_SLOT)  // 230656 B (< 232448 max)

__global__ void __launch_bounds__(NTHREADS, 1)
conv_mma_kernel(float* __restrict__ out)
{
    extern __shared__ char smem[];
    const uint32_t sb = smem_u32(smem);
    const int tid  = threadIdx.x;
    const int lane = tid & 31;
    const int wid  = tid >> 5;
    const int k0w  = (wid & 1) * 64;          // warp's out-channel base (GEMM m)
    const int q0w  = ((wid >> 1) & 1) * 64;   // warp's q base           (GEMM n)
    const int pp   = wid >> 2;                // warp's p parity within the pair

    const int n  = blockIdx.x / 9;            // image
    const int p0 = (blockIdx.x % 9) * 14;     // first output row of this CTA's chunk
    const __half* ibase = g_input_h + ((size_t)(n * H_IN + p0)) * (W_IN * C_IN);

    // ---- resident weight loads (9 x 128 x 128B, XOR-swizzled rows) ----
#pragma unroll 4
    for (int it = 0; it < 36; it++) {
        int i   = it * 256 + tid;              // 16B chunk index, [0, 9216)
        int ch  = i & 7;
        int row = (i >> 3) & 127;
        int rs  = i >> 10;
        uint32_t dst = sb + rs * W_SLOT + row * 128 + ((ch ^ (row & 7)) << 4);
        CP_ASYNC16(dst, g_w9 + (size_t)i * 8);
    }

    // ---- input row loader: global chunk row j (0..15) -> ring slot j%5 ----
    auto issue_row = [&](int j) {
        if (j >= 16) return;                   // tail pairs have no next row
        const __half* src = ibase + (size_t)j * (W_IN * C_IN);
        uint32_t slotb = sb + SM_IN_OFF + (j % NRING) * IN_SLOT;
#pragma unroll
        for (int it = 0; it < 5; it++) {
            int i = it * 256 + tid;            // [0, 1040) 16B chunks
            if (i < IN_ROWS * 8) {
                int row = i >> 3, ch = i & 7;
                uint32_t dst = slotb + row * 128 + ((ch ^ (row & 7)) << 4);
                CP_ASYNC16(dst, src + row * 64 + ch * 8);
            }
        }
    };

    issue_row(0); CP_COMMIT();                 // group also carries the weights
    issue_row(1); CP_COMMIT();
    issue_row(2); CP_COMMIT();
    issue_row(3); CP_COMMIT();

    float acc[4][8][4];
#pragma unroll
    for (int a = 0; a < 4; a++)
#pragma unroll
        for (int b = 0; b < 8; b++)
#pragma unroll
            for (int c = 0; c < 4; c++) acc[a][b][c] = 0.0f;

    // one r-stage of the warp's 64x64 tile; input row = ring slot `slot`,
    // weight vertical offset r (wslot = r*3+ss)
    auto compute_stage = [&](int slot, int r) {
        const uint32_t islot = sb + SM_IN_OFF + slot * IN_SLOT;
#pragma unroll
        for (int ss = 0; ss < 3; ss++) {
            const uint32_t wslot = sb + (r * 3 + ss) * W_SLOT;
#pragma unroll
            for (int kk = 0; kk < 4; kk++) {   // 16-deep c chunks
                uint32_t a[4][4];
#pragma unroll
                for (int mf = 0; mf < 4; mf++) { // A = weights [k][c], row-major
                    int row = k0w + 16 * mf + (lane & 15);
                    int ch  = kk * 2 + (lane >> 4);
                    LDSM_X4(a[mf], wslot + row * 128 + ((ch ^ (row & 7)) << 4));
                }
                uint32_t b[4][4];
#pragma unroll
                for (int nb = 0; nb < 4; nb++) { // B = input [q][c] row-major
                    int row = q0w + nb * 16 + (lane & 7) + ((lane >> 4) << 3) + ss;
                    int ch  = kk * 2 + ((lane >> 3) & 1);
                    LDSM_X4(b[nb], islot + row * 128 + ((ch ^ (row & 7)) << 4));
                }
#pragma unroll
                for (int mf = 0; mf < 4; mf++)
#pragma unroll
                    for (int nb = 0; nb < 4; nb++) {
                        MMA16816(acc[mf][nb * 2 + 0], a[mf], b[nb][0], b[nb][1]);
                        MMA16816(acc[mf][nb * 2 + 1], a[mf], b[nb][2], b[nb][3]);
                    }
            }
        }
    };

    for (int t = 0; t < NPAIRS; t++) {
        const int j0 = 2 * t;                  // pair uses chunk rows j0..j0+3

        CP_WAIT0();                            // rows <= j0+3 (and weights) resident
        __syncthreads();                       // ...visible to all; prior readers done
        issue_row(j0 + 4); CP_COMMIT();        // overwrites slot of dead row j0-1

        // r=0 : warp pp reads row j0+pp
        compute_stage((j0 + pp) % NRING, 0);

        __syncthreads();                       // row j0 dead after r=0
        issue_row(j0 + 5); CP_COMMIT();        // overwrites slot of row j0

        // r=1 : row j0+1+pp ; r=2 : row j0+2+pp   (all resident)
        compute_stage((j0 + 1 + pp) % NRING, 1);
        compute_stage((j0 + 2 + pp) % NRING, 2);

        // ---- epilogue: warp's 64x64 -> out[n][k][p0+j0+pp][q], float2 stores ----
        {
            const int p = p0 + j0 + pp;
            float* ob = out + (size_t)n * K_OUT * PQ + (size_t)p * Q_OUT;
            const int lr = lane >> 2, lc = (lane & 3) * 2;
#pragma unroll
            for (int mf = 0; mf < 4; mf++) {
#pragma unroll
                for (int nf = 0; nf < 8; nf++) {
                    int k = k0w + 16 * mf + lr;
                    int q = q0w + 8 * nf + lc;
                    if (q < Q_OUT) {
                        float2 v0 = make_float2(acc[mf][nf][0], acc[mf][nf][1]);
                        float2 v1 = make_float2(acc[mf][nf][2], acc[mf][nf][3]);
                        *(float2*)(ob + (size_t)k * PQ + q)       = v0;
                        *(float2*)(ob + (size_t)(k + 8) * PQ + q) = v1;
                    }
                    acc[mf][nf][0] = acc[mf][nf][1] = acc[mf][nf][2] = acc[mf][nf][3] = 0.0f;
                }
            }
        }
    }
}

// ---------------- host launch ----------------
extern "C" void kernel_launch(void* const* d_in, const int* in_sizes, int n_in,
                              void* d_out, int out_size)
{
    const float* data = (const float*)d_in[0];   // [16,64,128,128] f32
    const float* wts  = (const float*)d_in[1];   // [128,64,3,3]  f32
    float* out        = (float*)d_out;           // [16,128,126,126] f32

    convert_weights_kernel<<<(9 * K_OUT * C_IN + 255) / 256, 256>>>(wts);
    convert_input_kernel<<<dim3(W_IN / 32, H_IN, NB), 256>>>(data);

    static bool attr_set = false;
    if (!attr_set) {
        cudaFuncSetAttribute(conv_mma_kernel,
                             cudaFuncAttributeMaxDynamicSharedMemorySize, SM_TOTAL);
        attr_set = true;
    }
    conv_mma_kernel<<<NCTA, NTHREADS, SM_TOTAL>>>(out);
}

// round 10
// speedup vs baseline: 1.0140x; 1.0140x over previous
#include <cuda_runtime.h>
#include <cuda_fp16.h>
#include <cstdint>

// Problem shapes
#define NB    16
#define C_IN  64
#define H_IN  128
#define W_IN  128
#define K_OUT 128
#define P_OUT 126
#define Q_OUT 126
#define PQ    (P_OUT * Q_OUT)

// ---------------- scratch (device globals: allocation-free) ----------------
// +1024 halves of pad: row-ring loads read up to 2 q-rows past the last image row.
__device__ __align__(1024) __half g_input_h[(size_t)NB * H_IN * W_IN * C_IN + 1024]; // NHWC fp16
__device__ __align__(1024) __half g_w9[9 * K_OUT * C_IN];                             // [rs][k][c]

// ---------------- PTX helpers (all sm_80-level: works on compute_103) ----------------
__device__ __forceinline__ uint32_t smem_u32(const void* p) {
    uint32_t a;
    asm("{ .reg .u64 t; cvta.to.shared.u64 t, %1; cvt.u32.u64 %0, t; }" : "=r"(a) : "l"(p));
    return a;
}

#define CP_ASYNC16(dst, src) \
    asm volatile("cp.async.cg.shared.global [%0], [%1], 16;\n" :: "r"(dst), "l"(src) : "memory")
#define CP_COMMIT() asm volatile("cp.async.commit_group;\n" ::: "memory")
#define CP_WAIT0()  asm volatile("cp.async.wait_group 0;\n" ::: "memory")

#define LDSM_X4(R, addr) \
    asm volatile("ldmatrix.sync.aligned.m8n8.x4.shared.b16 {%0,%1,%2,%3}, [%4];\n" \
        : "=r"((R)[0]), "=r"((R)[1]), "=r"((R)[2]), "=r"((R)[3]) : "r"(addr))

#define MMA16816(C, A, B0, B1) \
    asm volatile("mma.sync.aligned.m16n8k16.row.col.f32.f16.f16.f32 " \
        "{%0,%1,%2,%3}, {%4,%5,%6,%7}, {%8,%9}, {%0,%1,%2,%3};\n" \
        : "+f"((C)[0]), "+f"((C)[1]), "+f"((C)[2]), "+f"((C)[3]) \
        : "r"((A)[0]), "r"((A)[1]), "r"((A)[2]), "r"((A)[3]), "r"(B0), "r"(B1))

// ---------------- prologue kernels ----------------
// NCHW f32 -> NHWC fp16 (tiled transpose through smem)
__global__ void convert_input_kernel(const float* __restrict__ data) {
    __shared__ float s[64 * 33];
    const int w0 = blockIdx.x * 32, h = blockIdx.y, n = blockIdx.z;
    const int tid = threadIdx.x;
#pragma unroll
    for (int it = 0; it < 8; it++) {
        int i = it * 256 + tid;
        int c = i >> 5, w = i & 31;
        s[c * 33 + w] = data[(((size_t)n * C_IN + c) * H_IN + h) * W_IN + w0 + w];
    }
    __syncthreads();
    __half2* gp = (__half2*)g_input_h;
#pragma unroll
    for (int it = 0; it < 4; it++) {
        int i = it * 256 + tid;
        int w = i >> 5, cp = i & 31;
        float lo = s[(2 * cp) * 33 + w];
        float hi = s[(2 * cp + 1) * 33 + w];
        gp[(((size_t)n * H_IN + h) * W_IN + w0 + w) * 32 + cp] = __floats2half2_rn(lo, hi);
    }
}

// W[k,c,r,s] f32 -> g_w9[rs][k][c] fp16
__global__ void convert_weights_kernel(const float* __restrict__ w) {
    int i = blockIdx.x * 256 + threadIdx.x;
    if (i >= 9 * K_OUT * C_IN) return;
    int rs = i / (K_OUT * C_IN);
    int rem = i - rs * (K_OUT * C_IN);
    int k = rem >> 6, c = rem & 63;
    int r = rs / 3, s = rs - r * 3;
    g_w9[i] = __float2half(w[((k * C_IN + c) * 3 + r) * 3 + s]);
}

// ---------------- main mma.sync conv kernel ----------------
// 8 warps (2/SMSP), warp = (k-half, q-half, p-parity), each 64(k) x 64(q).
// CTA owns 14 CONTIGUOUS output rows of one image -> sliding 5-slot input
// row ring, each input row loaded exactly once (16 loads / 14 output rows).
#define NTHREADS 256
#define NCTA 144                      // 16 images x 9 chunks of 14 rows
#define NPAIRS 7                      // 7 row-pairs per CTA
#define W_SLOT 16384                  // 128 rows(k) x 128B(64 halves)
#define IN_ROWS 130                   // q-rows per input image row (incl. 2 pad reads)
#define IN_SLOT (IN_ROWS * 128)       // 16640 B
#define NRING 5
#define SM_IN_OFF (9 * W_SLOT)        // 147456
#define SM_TOTAL (SM_IN_OFF + NRING * IN_SLOT)  // 230656 B (< 232448 max)

__global__ void __launch_bounds__(NTHREADS, 1)
conv_mma_kernel(float* __restrict__ out)
{
    extern __shared__ char smem[];
    const uint32_t sb = smem_u32(smem);
    const int tid  = threadIdx.x;
    const int lane = tid & 31;
    const int wid  = tid >> 5;
    const int k0w  = (wid & 1) * 64;          // warp's out-channel base (GEMM m)
    const int q0w  = ((wid >> 1) & 1) * 64;   // warp's q base           (GEMM n)
    const int pp   = wid >> 2;                // warp's p parity within the pair

    const int n  = blockIdx.x / 9;            // image
    const int p0 = (blockIdx.x % 9) * 14;     // first output row of this CTA's chunk
    const __half* ibase = g_input_h + ((size_t)(n * H_IN + p0)) * (W_IN * C_IN);

    // ---- resident weight loads (9 x 128 x 128B, XOR-swizzled rows) ----
#pragma unroll 4
    for (int it = 0; it < 36; it++) {
        int i   = it * 256 + tid;              // 16B chunk index, [0, 9216)
        int ch  = i & 7;
        int row = (i >> 3) & 127;
        int rs  = i >> 10;
        uint32_t dst = sb + rs * W_SLOT + row * 128 + ((ch ^ (row & 7)) << 4);
        CP_ASYNC16(dst, g_w9 + (size_t)i * 8);
    }

    // ---- input row loader: global chunk row j (0..15) -> ring slot j%5 ----
    auto issue_row = [&](int j) {
        if (j >= 16) return;                   // tail pairs have no next row
        const __half* src = ibase + (size_t)j * (W_IN * C_IN);
        uint32_t slotb = sb + SM_IN_OFF + (j % NRING) * IN_SLOT;
#pragma unroll
        for (int it = 0; it < 5; it++) {
            int i = it * 256 + tid;            // [0, 1040) 16B chunks
            if (i < IN_ROWS * 8) {
                int row = i >> 3, ch = i & 7;
                uint32_t dst = slotb + row * 128 + ((ch ^ (row & 7)) << 4);
                CP_ASYNC16(dst, src + row * 64 + ch * 8);
            }
        }
    };

    issue_row(0); CP_COMMIT();                 // group also carries the weights
    issue_row(1); CP_COMMIT();
    issue_row(2); CP_COMMIT();
    issue_row(3); CP_COMMIT();

    float acc[4][8][4];
#pragma unroll
    for (int a = 0; a < 4; a++)
#pragma unroll
        for (int b = 0; b < 8; b++)
#pragma unroll
            for (int c = 0; c < 4; c++) acc[a][b][c] = 0.0f;

    // one r-stage of the warp's 64x64 tile; input row = ring slot `slot`,
    // weight vertical offset r (wslot = r*3+ss)
    auto compute_stage = [&](int slot, int r) {
        const uint32_t islot = sb + SM_IN_OFF + slot * IN_SLOT;
#pragma unroll
        for (int ss = 0; ss < 3; ss++) {
            const uint32_t wslot = sb + (r * 3 + ss) * W_SLOT;
#pragma unroll
            for (int kk = 0; kk < 4; kk++) {   // 16-deep c chunks
                uint32_t a[4][4];
#pragma unroll
                for (int mf = 0; mf < 4; mf++) { // A = weights [k][c], row-major
                    int row = k0w + 16 * mf + (lane & 15);
                    int ch  = kk * 2 + (lane >> 4);
                    LDSM_X4(a[mf], wslot + row * 128 + ((ch ^ (row & 7)) << 4));
                }
                uint32_t b[4][4];
#pragma unroll
                for (int nb = 0; nb < 4; nb++) { // B = input [q][c] row-major
                    int row = q0w + nb * 16 + (lane & 7) + ((lane >> 4) << 3) + ss;
                    int ch  = kk * 2 + ((lane >> 3) & 1);
                    LDSM_X4(b[nb], islot + row * 128 + ((ch ^ (row & 7)) << 4));
                }
#pragma unroll
                for (int mf = 0; mf < 4; mf++)
#pragma unroll
                    for (int nb = 0; nb < 4; nb++) {
                        MMA16816(acc[mf][nb * 2 + 0], a[mf], b[nb][0], b[nb][1]);
                        MMA16816(acc[mf][nb * 2 + 1], a[mf], b[nb][2], b[nb][3]);
                    }
            }
        }
    };

    for (int t = 0; t < NPAIRS; t++) {
        const int j0 = 2 * t;                  // pair uses chunk rows j0..j0+3

        CP_WAIT0();                            // rows <= j0+3 (and weights) resident
        __syncthreads();                       // ...visible to all; prior readers done
        issue_row(j0 + 4); CP_COMMIT();        // overwrites slot of dead row j0-1

        // r=0 : warp pp reads row j0+pp
        compute_stage((j0 + pp) % NRING, 0);

        __syncthreads();                       // row j0 dead after r=0
        issue_row(j0 + 5); CP_COMMIT();        // overwrites slot of row j0

        // r=1 : row j0+1+pp ; r=2 : row j0+2+pp   (all resident)
        compute_stage((j0 + 1 + pp) % NRING, 1);
        compute_stage((j0 + 2 + pp) % NRING, 2);

        // ---- epilogue: warp's 64x64 -> out[n][k][p0+j0+pp][q], float2 stores ----
        {
            const int p = p0 + j0 + pp;
            float* ob = out + (size_t)n * K_OUT * PQ + (size_t)p * Q_OUT;
            const int lr = lane >> 2, lc = (lane & 3) * 2;
#pragma unroll
            for (int mf = 0; mf < 4; mf++) {
#pragma unroll
                for (int nf = 0; nf < 8; nf++) {
                    int k = k0w + 16 * mf + lr;
                    int q = q0w + 8 * nf + lc;
                    if (q < Q_OUT) {
                        float2 v0 = make_float2(acc[mf][nf][0], acc[mf][nf][1]);
                        float2 v1 = make_float2(acc[mf][nf][2], acc[mf][nf][3]);
                        *(float2*)(ob + (size_t)k * PQ + q)       = v0;
                        *(float2*)(ob + (size_t)(k + 8) * PQ + q) = v1;
                    }
                    acc[mf][nf][0] = acc[mf][nf][1] = acc[mf][nf][2] = acc[mf][nf][3] = 0.0f;
                }
            }
        }
    }
}

// ---------------- host launch ----------------
extern "C" void kernel_launch(void* const* d_in, const int* in_sizes, int n_in,
                              void* d_out, int out_size)
{
    const float* data = (const float*)d_in[0];   // [16,64,128,128] f32
    const float* wts  = (const float*)d_in[1];   // [128,64,3,3]  f32
    float* out        = (float*)d_out;           // [16,128,126,126] f32

    convert_weights_kernel<<<(9 * K_OUT * C_IN + 255) / 256, 256>>>(wts);
    convert_input_kernel<<<dim3(W_IN / 32, H_IN, NB), 256>>>(data);

    static bool attr_set = false;
    if (!attr_set) {
        cudaFuncSetAttribute(conv_mma_kernel,
                             cudaFuncAttributeMaxDynamicSharedMemorySize, SM_TOTAL);
        attr_set = true;
    }
    conv_mma_kernel<<<NCTA, NTHREADS, SM_TOTAL>>>(out);
}